// round 15
// baseline (speedup 1.0000x reference)
#include <cuda_runtime.h>
#include <math.h>

#define BATCH 32
#define CH    64
#define HH    256
#define WW    256
#define NCHAN 2048

__device__ float g_red[5 * NCHAN];   // [0]=sum(x) [1]=S0 [2]=T0 [3]=S1 [4]=T1
__device__ unsigned int g_cnt = 0;

// ---- head scratch (global; used by the last block only) ----
#define OFF_FC1W 0
#define OFF_FC2W 2048
#define OFF_Z    4096
#define OFF_H    6144
#define OFF_WSM  7168
#define OFF_C1W  9216
#define OFF_C2W  9472
#define OFF_F1B  10112
#define OFF_F2B  10144
#define OFF_C1B  10208
#define OFF_C2B  10336
#define OFF_FBUF 10344
#define HEAD_FLOATS 10416
__device__ __align__(16) float g_head[HEAD_FLOATS];

// packed f32x2 helpers (Blackwell FADD2/FFMA2 via PTX)
#define PACK2(d, lo, hi)  asm("mov.b64 %0, {%1, %2};" : "=l"(d) : "f"(lo), "f"(hi))
#define UNPK2(lo, hi, s)  asm("mov.b64 {%0, %1}, %2;" : "=f"(lo), "=f"(hi) : "l"(s))
#define ADDX2(d, a, b)    asm("add.rn.f32x2 %0, %1, %2;" : "=l"(d) : "l"(a), "l"(b))
#define FMAX2(d, a, b, c) asm("fma.rn.f32x2 %0, %1, %2, %3;" : "=l"(d) : "l"(a), "l"(b), "l"(c))

#define PF_L1(p) asm volatile("prefetch.global.L1 [%0];" :: "l"(p))

__device__ __forceinline__ void load8(const float* __restrict__ p, float* __restrict__ v) {
    float4 a = *(const float4*)p;
    float4 b = *(const float4*)(p + 4);
    v[0]=a.x; v[1]=a.y; v[2]=a.z; v[3]=a.w;
    v[4]=b.x; v[5]=b.y; v[6]=b.z; v[7]=b.w;
}

// Phase-P step: cur = v[P] (row r), next = v[(P+1)%3] (row r+1),
// prefetch row r+2 into v[(P+2)%3]; L1-prefetch row r+4 (2-row lead).
// With smem freed, L1D ~227KB per SM holds the whole per-SM stream window,
// so the prefetched lines survive until their demand loads (L1 hits).
template<int P>
__device__ __forceinline__ void topo_step(
    const float* __restrict__ pf, bool eL, bool eR,
    float (&v)[3][8], float (&prx)[8], float (&prn)[8],
    unsigned long long& Z01, unsigned long long& S01, unsigned long long& T01,
    unsigned long long eps2)
{
    constexpr int C = P;
    constexpr int N = (P + 1) % 3;
    constexpr int F = (P + 2) % 3;
    load8(pf, v[F]);
    PF_L1(pf + 2 * WW);

    const float* cur = v[C];
    const float* nx  = v[N];

    // vertical 3-row results for edge columns first (feed shuffles early)
    float vx7 = fmaxf(prx[7], nx[7]);
    float vn7 = fminf(prn[7], nx[7]);
    float vx0 = fmaxf(prx[0], nx[0]);
    float vn0 = fminf(prn[0], nx[0]);

    float Lxr = __shfl_up_sync(0xffffffffu, vx7, 1);
    float Lnr = __shfl_up_sync(0xffffffffu, vn7, 1);
    float Rxr = __shfl_down_sync(0xffffffffu, vx0, 1);
    float Rnr = __shfl_down_sync(0xffffffffu, vn0, 1);
    float ax = eL ? -INFINITY : Lxr;
    float an = eL ?  INFINITY : Lnr;
    float Rx = eR ? -INFINITY : Rxr;
    float Rn = eR ?  INFINITY : Rnr;

    float bx = vx0, bn = vn0;
    #pragma unroll
    for (int i = 0; i < 8; ++i) {
        float cx = (i < 7) ? fmaxf(prx[i+1], nx[i+1]) : Rx;
        float cn = (i < 7) ? fminf(prn[i+1], nx[i+1]) : Rn;
        float mx = fmaxf(ax, fmaxf(bx, cx));
        float mn = fminf(an, fminf(bn, cn));
        float y  = cur[i];
        float l0 = mx - y;
        float l1 = y - mn;
        unsigned long long l01, le01, lg01;
        PACK2(l01, l0, l1);
        ADDX2(le01, l01, eps2);            // (l0+eps, l1+eps)
        float le0, le1;
        UNPK2(le0, le1, le01);
        float lg0 = __log2f(le0);
        float lg1 = __log2f(le1);
        PACK2(lg01, lg0, lg1);
        ADDX2(S01, S01, l01);              // (S0,S1) += (l0,l1)
        FMAX2(T01, l01, lg01, T01);        // (T0,T1) += (l0,l1)*(lg0,lg1)
        ax = bx; bx = cx;
        an = bn; bn = cn;
    }
    // zacc over cur row: float4-aligned register pairs
    #pragma unroll
    for (int j = 0; j < 4; ++j) {
        unsigned long long y01;
        PACK2(y01, cur[2*j], cur[2*j+1]);
        ADDX2(Z01, Z01, y01);
    }
    #pragma unroll
    for (int i = 0; i < 8; ++i) {
        prx[i] = fmaxf(cur[i], nx[i]);
        prn[i] = fminf(cur[i], nx[i]);
    }
}

__global__ __launch_bounds__(256, 4)
void topo_fused_kernel(const float* __restrict__ x,
                       const float* __restrict__ fc1_w, const float* __restrict__ fc1_b,
                       const float* __restrict__ fc2_w, const float* __restrict__ fc2_b,
                       const float* __restrict__ cls1_w, const float* __restrict__ cls1_b,
                       const float* __restrict__ cls2_w, const float* __restrict__ cls2_b,
                       float* __restrict__ out)
{
    __shared__ float red[48];
    __shared__ int s_last;

    const int ch   = blockIdx.x;
    const int tid  = threadIdx.x;
    const int wrp  = tid >> 5;
    const int lane = tid & 31;
    const bool eL = (lane == 0), eR = (lane == 31);
    const float* __restrict__ base = x + (size_t)ch * (HH * WW) + lane * 8;

    const int r0 = wrp * 32;                   // output rows r0 .. r0+31
    const int ra = (r0 == 0) ? 0 : (r0 - 1);

    float v[3][8], prx[8], prn[8];
    unsigned long long Z01 = 0, S01 = 0, T01 = 0, eps2;
    {
        float e = 1e-35f;
        PACK2(eps2, e, e);
    }

    {
        float vp[8];
        load8(base + ra * WW, vp);             // row r0-1 (clamped)
        load8(base + r0 * WW, v[0]);           // cur  = row r0
        load8(base + (r0 + 1) * WW, v[1]);     // next = row r0+1
        #pragma unroll
        for (int i = 0; i < 8; ++i) {
            prx[i] = fmaxf(vp[i], v[0][i]);
            prn[i] = fminf(vp[i], v[0][i]);
        }
    }

    // Main loop: 30 uniform steps (loads rows r0+2 .. r0+31, never OOB).
    const float* p = base + (r0 + 2) * WW;
    #pragma unroll 1
    for (int g = 0; g < 10; ++g) {
        topo_step<0>(p,        eL, eR, v, prx, prn, Z01, S01, T01, eps2);
        topo_step<1>(p + WW,   eL, eR, v, prx, prn, Z01, S01, T01, eps2);
        topo_step<2>(p + 2*WW, eL, eR, v, prx, prn, Z01, S01, T01, eps2);
        p += 3 * WW;
    }
    // Tail: out rows r0+30, r0+31; loads clamp to row 255 (warp 7 only).
    {
        const float* p30 = base + ((r0 + 32 > 255) ? 255 : (r0 + 32)) * WW;
        const float* p31 = base + ((r0 + 33 > 255) ? 255 : (r0 + 33)) * WW;
        topo_step<0>(p30, eL, eR, v, prx, prn, Z01, S01, T01, eps2);
        topo_step<1>(p31, eL, eR, v, prx, prn, Z01, S01, T01, eps2);
    }

    float za, zb, S0, S1, T0, T1;
    UNPK2(za, zb, Z01);
    UNPK2(S0, S1, S01);
    UNPK2(T0, T1, T01);
    float zacc = za + zb;

    // warp reduce 5 accumulators
    #pragma unroll
    for (int o = 16; o; o >>= 1) {
        zacc += __shfl_down_sync(0xffffffffu, zacc, o);
        S0   += __shfl_down_sync(0xffffffffu, S0,   o);
        T0   += __shfl_down_sync(0xffffffffu, T0,   o);
        S1   += __shfl_down_sync(0xffffffffu, S1,   o);
        T1   += __shfl_down_sync(0xffffffffu, T1,   o);
    }
    if (lane == 0) {
        red[0*8 + wrp] = zacc;
        red[1*8 + wrp] = S0;
        red[2*8 + wrp] = T0 * 0.69314718056f;  // log2 -> ln
        red[3*8 + wrp] = S1;
        red[4*8 + wrp] = T1 * 0.69314718056f;
    }
    __syncthreads();
    if (tid < 5) {
        float a = 0.f;
        #pragma unroll
        for (int j = 0; j < 8; ++j) a += red[tid*8 + j];
        g_red[tid * NCHAN + ch] = a;
    }
    __threadfence();
    __syncthreads();
    if (tid == 0) s_last = (atomicAdd(&g_cnt, 1u) == (unsigned)(gridDim.x - 1));
    __syncthreads();
    if (!s_last) return;

    // ======================= HEAD (last block only) =======================
    __threadfence();
    float* GH = g_head;

    for (int i = tid; i < 512; i += 256) ((float4*)(GH+OFF_FC1W))[i] = ((const float4*)fc1_w)[i];
    for (int i = tid; i < 512; i += 256) ((float4*)(GH+OFF_FC2W))[i] = ((const float4*)fc2_w)[i];
    for (int i = tid; i < 64;  i += 256) ((float4*)(GH+OFF_C1W))[i]  = ((const float4*)cls1_w)[i];
    for (int i = tid; i < 160; i += 256) ((float4*)(GH+OFF_C2W))[i]  = ((const float4*)cls2_w)[i];
    if (tid < 32)  GH[OFF_F1B + tid] = fc1_b[tid];
    if (tid < 64)  GH[OFF_F2B + tid] = fc2_b[tid];
    if (tid < 128) GH[OFF_C1B + tid] = cls1_b[tid];
    if (tid < 5)   GH[OFF_C2B + tid] = cls2_b[tid];
    for (int i = tid; i < NCHAN; i += 256) {       // z transposed z_T[c][b]
        int c = i >> 5, b = i & 31;
        GH[OFF_Z + i] = __ldcg(&g_red[b * CH + c]) * (1.f / 65536.f);
    }
    __syncthreads();

    // h_T[j][b] = relu(z @ fc1_w^T + b)
    for (int i = tid; i < BATCH * 32; i += 256) {
        int j = i >> 5, b = i & 31;
        float acc = GH[OFF_F1B + j];
        const float* wr = GH + OFF_FC1W + j * CH;
        #pragma unroll
        for (int c = 0; c < CH; ++c) acc += GH[OFF_Z + c*32 + b] * wr[c];
        GH[OFF_H + j*32 + b] = fmaxf(acc, 0.f);
    }
    __syncthreads();

    // pre-softmax logits
    for (int i = tid; i < NCHAN; i += 256) {
        int c = i >> 5, b = i & 31;
        float acc = GH[OFF_F2B + c];
        const float* wr = GH + OFF_FC2W + c * 32;
        #pragma unroll
        for (int j = 0; j < 32; ++j) acc += GH[OFF_H + j*32 + b] * wr[j];
        GH[OFF_WSM + b*CH + c] = acc;
    }
    __syncthreads();

    // softmax per row
    for (int b = wrp; b < BATCH; b += 8) {
        float v0 = GH[OFF_WSM + b*CH + lane];
        float v1 = GH[OFF_WSM + b*CH + 32 + lane];
        float m = fmaxf(v0, v1);
        #pragma unroll
        for (int o = 16; o; o >>= 1) m = fmaxf(m, __shfl_xor_sync(0xffffffffu, m, o));
        float e0 = __expf(v0 - m), e1 = __expf(v1 - m);
        float s = e0 + e1;
        #pragma unroll
        for (int o = 16; o; o >>= 1) s += __shfl_xor_sync(0xffffffffu, s, o);
        float inv = 1.f / s;
        GH[OFF_WSM + b*CH + lane]      = e0 * inv;
        GH[OFF_WSM + b*CH + 32 + lane] = e1 * inv;
    }
    __syncthreads();

    // entropy closed form, write w
    for (int i = tid; i < NCHAN; i += 256) {
        float wv = GH[OFF_WSM + i];
        out[BATCH*5 + i] = wv;
        float s0v = __ldcg(&g_red[1*NCHAN + i]);
        float t0v = __ldcg(&g_red[2*NCHAN + i]);
        float s1v = __ldcg(&g_red[3*NCHAN + i]);
        float t1v = __ldcg(&g_red[4*NCHAN + i]);
        float lw = __logf(wv);
        float a0 = wv * s0v, s0 = a0 + 1e-12f;
        float e0 = (a0 / s0) * (__logf(s0) - lw) - wv * t0v / s0;
        float a1 = wv * s1v, s1 = a1 + 1e-12f;
        float e1 = (a1 / s1) * (__logf(s1) - lw) - wv * t1v / s1;
        GH[OFF_FC1W + i] = e0 * wv;
        GH[OFF_FC2W + i] = e1 * wv;
    }
    __syncthreads();

    if (tid < BATCH * 2) {
        int b = tid >> 1, k = tid & 1;
        const float* cs = GH + (k == 0 ? OFF_FC1W : OFF_FC2W) + b*CH;
        float acc = 0.f, ws = 0.f;
        #pragma unroll
        for (int c = 0; c < CH; ++c) { acc += cs[c]; ws += GH[OFF_WSM + b*CH + c]; }
        float fv = acc / (ws + 1e-6f);
        GH[OFF_FBUF + tid] = fv;
        out[BATCH*5 + NCHAN + tid] = fv;
    }
    __syncthreads();

    for (int i = tid; i < BATCH * 128; i += 256) {
        int b = i >> 7, j = i & 127;
        float mv = GH[OFF_FBUF + 2*b] * GH[OFF_C1W + 2*j]
                 + GH[OFF_FBUF + 2*b + 1] * GH[OFF_C1W + 2*j + 1]
                 + GH[OFF_C1B + j];
        GH[OFF_Z + i] = fmaxf(mv, 0.f);
    }
    __syncthreads();

    for (int i = tid; i < BATCH * 5; i += 256) {
        int b = i / 5, n = i - b * 5;
        float acc = GH[OFF_C2B + n];
        const float* wr = GH + OFF_C2W + n * 128;
        const float* mr = GH + OFF_Z + b * 128;
        #pragma unroll
        for (int j = 0; j < 128; ++j) acc += mr[j] * wr[j];
        out[i] = acc;
    }
    if (tid == 0) g_cnt = 0;
}

extern "C" void kernel_launch(void* const* d_in, const int* in_sizes, int n_in,
                              void* d_out, int out_size) {
    const float* x      = (const float*)d_in[0];
    const float* fc1_w  = (const float*)d_in[1];
    const float* fc1_b  = (const float*)d_in[2];
    const float* fc2_w  = (const float*)d_in[3];
    const float* fc2_b  = (const float*)d_in[4];
    const float* cls1_w = (const float*)d_in[5];
    const float* cls1_b = (const float*)d_in[6];
    const float* cls2_w = (const float*)d_in[7];
    const float* cls2_b = (const float*)d_in[8];
    float* out = (float*)d_out;

    topo_fused_kernel<<<NCHAN, 256>>>(x, fc1_w, fc1_b, fc2_w, fc2_b,
                                      cls1_w, cls1_b, cls2_w, cls2_b, out);
}

// round 16
// speedup vs baseline: 1.0255x; 1.0255x over previous
#include <cuda_runtime.h>
#include <math.h>

#define BATCH 32
#define CH    64
#define HH    256
#define WW    256
#define NCHAN 2048

__device__ float g_red[5 * NCHAN];   // [0]=sum(x) [1]=S0 [2]=T0 [3]=S1 [4]=T1
__device__ unsigned int g_cnt = 0;

// ---- shared memory layout (floats) ----
#define OFF_FC1W 0
#define OFF_FC2W 2048
#define OFF_Z    4096
#define OFF_H    6144
#define OFF_WSM  7168
#define OFF_C1W  9216
#define OFF_C2W  9472
#define OFF_F1B  10112
#define OFF_F2B  10144
#define OFF_C1B  10208
#define OFF_C2B  10336
#define OFF_FBUF 10344
#define SMEM_FLOATS 10416

// packed f32x2 helpers (Blackwell FADD2/FFMA2 via PTX)
#define PACK2(d, lo, hi)  asm("mov.b64 %0, {%1, %2};" : "=l"(d) : "f"(lo), "f"(hi))
#define UNPK2(lo, hi, s)  asm("mov.b64 {%0, %1}, %2;" : "=f"(lo), "=f"(hi) : "l"(s))
#define ADDX2(d, a, b)    asm("add.rn.f32x2 %0, %1, %2;" : "=l"(d) : "l"(a), "l"(b))
#define FMAX2(d, a, b, c) asm("fma.rn.f32x2 %0, %1, %2, %3;" : "=l"(d) : "l"(a), "l"(b), "l"(c))

#define PF_L2(p) asm volatile("prefetch.global.L2 [%0];" :: "l"(p))

__device__ __forceinline__ void load8(const float* __restrict__ p, float* __restrict__ v) {
    float4 a = *(const float4*)p;
    float4 b = *(const float4*)(p + 4);
    v[0]=a.x; v[1]=a.y; v[2]=a.z; v[3]=a.w;
    v[4]=b.x; v[5]=b.y; v[6]=b.z; v[7]=b.w;
}

// Phase-P step: cur = v[P] (row r), next = v[(P+1)%3] (row r+1),
// prefetch row r+2 into v[(P+2)%3]; L2-prefetch row r+4 (distance-2, proven optimum).
template<int P>
__device__ __forceinline__ void topo_step(
    const float* __restrict__ pf, bool eL, bool eR,
    float (&v)[3][8], float (&prx)[8], float (&prn)[8],
    unsigned long long& Z01, unsigned long long& S01, unsigned long long& T01,
    unsigned long long eps2)
{
    constexpr int C = P;
    constexpr int N = (P + 1) % 3;
    constexpr int F = (P + 2) % 3;
    load8(pf, v[F]);
    PF_L2(pf + 2 * WW);

    const float* cur = v[C];
    const float* nx  = v[N];

    // vertical 3-row results for edge columns first (feed shuffles early)
    float vx7 = fmaxf(prx[7], nx[7]);
    float vn7 = fminf(prn[7], nx[7]);
    float vx0 = fmaxf(prx[0], nx[0]);
    float vn0 = fminf(prn[0], nx[0]);

    float Lxr = __shfl_up_sync(0xffffffffu, vx7, 1);
    float Lnr = __shfl_up_sync(0xffffffffu, vn7, 1);
    float Rxr = __shfl_down_sync(0xffffffffu, vx0, 1);
    float Rnr = __shfl_down_sync(0xffffffffu, vn0, 1);
    float ax = eL ? -INFINITY : Lxr;
    float an = eL ?  INFINITY : Lnr;
    float Rx = eR ? -INFINITY : Rxr;
    float Rn = eR ?  INFINITY : Rnr;

    float bx = vx0, bn = vn0;
    #pragma unroll
    for (int i = 0; i < 8; ++i) {
        float cx = (i < 7) ? fmaxf(prx[i+1], nx[i+1]) : Rx;
        float cn = (i < 7) ? fminf(prn[i+1], nx[i+1]) : Rn;
        float mx = fmaxf(ax, fmaxf(bx, cx));
        float mn = fminf(an, fminf(bn, cn));
        float y  = cur[i];
        float l0 = mx - y;
        float l1 = y - mn;
        unsigned long long l01, le01, lg01;
        PACK2(l01, l0, l1);
        ADDX2(le01, l01, eps2);            // (l0+eps, l1+eps)
        float le0, le1;
        UNPK2(le0, le1, le01);
        float lg0 = __log2f(le0);
        float lg1 = __log2f(le1);
        PACK2(lg01, lg0, lg1);
        ADDX2(S01, S01, l01);              // (S0,S1) += (l0,l1)
        FMAX2(T01, l01, lg01, T01);        // (T0,T1) += (l0,l1)*(lg0,lg1)
        ax = bx; bx = cx;
        an = bn; bn = cn;
    }
    // zacc over cur row: float4-aligned register pairs
    #pragma unroll
    for (int j = 0; j < 4; ++j) {
        unsigned long long y01;
        PACK2(y01, cur[2*j], cur[2*j+1]);
        ADDX2(Z01, Z01, y01);
    }
    #pragma unroll
    for (int i = 0; i < 8; ++i) {
        prx[i] = fmaxf(cur[i], nx[i]);
        prn[i] = fminf(cur[i], nx[i]);
    }
}

__global__ __launch_bounds__(256, 4)
void topo_fused_kernel(const float* __restrict__ x,
                       const float* __restrict__ fc1_w, const float* __restrict__ fc1_b,
                       const float* __restrict__ fc2_w, const float* __restrict__ fc2_b,
                       const float* __restrict__ cls1_w, const float* __restrict__ cls1_b,
                       const float* __restrict__ cls2_w, const float* __restrict__ cls2_b,
                       float* __restrict__ out)
{
    __shared__ __align__(16) float S[SMEM_FLOATS];
    __shared__ int s_last;

    const int ch   = blockIdx.x;
    const int tid  = threadIdx.x;
    const int wrp  = tid >> 5;
    const int lane = tid & 31;
    const bool eL = (lane == 0), eR = (lane == 31);
    const float* __restrict__ base = x + (size_t)ch * (HH * WW) + lane * 8;

    const int r0 = wrp * 32;                   // output rows r0 .. r0+31
    const int ra = (r0 == 0) ? 0 : (r0 - 1);

    float v[3][8], prx[8], prn[8];
    unsigned long long Z01 = 0, S01 = 0, T01 = 0, eps2;
    {
        float e = 1e-35f;
        PACK2(eps2, e, e);
    }

    {
        float vp[8];
        load8(base + ra * WW, vp);             // row r0-1 (clamped)
        load8(base + r0 * WW, v[0]);           // cur  = row r0
        load8(base + (r0 + 1) * WW, v[1]);     // next = row r0+1
        #pragma unroll
        for (int i = 0; i < 8; ++i) {
            prx[i] = fmaxf(vp[i], v[0][i]);
            prn[i] = fminf(vp[i], v[0][i]);
        }
    }

    // Main loop: 30 uniform steps (loads rows r0+2 .. r0+31, never OOB).
    const float* p = base + (r0 + 2) * WW;
    #pragma unroll 1
    for (int g = 0; g < 10; ++g) {
        topo_step<0>(p,        eL, eR, v, prx, prn, Z01, S01, T01, eps2);
        topo_step<1>(p + WW,   eL, eR, v, prx, prn, Z01, S01, T01, eps2);
        topo_step<2>(p + 2*WW, eL, eR, v, prx, prn, Z01, S01, T01, eps2);
        p += 3 * WW;
    }
    // Tail: out rows r0+30, r0+31; loads clamp to row 255 (warp 7 only).
    {
        const float* p30 = base + ((r0 + 32 > 255) ? 255 : (r0 + 32)) * WW;
        const float* p31 = base + ((r0 + 33 > 255) ? 255 : (r0 + 33)) * WW;
        topo_step<0>(p30, eL, eR, v, prx, prn, Z01, S01, T01, eps2);
        topo_step<1>(p31, eL, eR, v, prx, prn, Z01, S01, T01, eps2);
    }

    float za, zb, S0, S1, T0, T1;
    UNPK2(za, zb, Z01);
    UNPK2(S0, S1, S01);
    UNPK2(T0, T1, T01);
    float zacc = za + zb;

    // warp reduce 5 accumulators
    #pragma unroll
    for (int o = 16; o; o >>= 1) {
        zacc += __shfl_down_sync(0xffffffffu, zacc, o);
        S0   += __shfl_down_sync(0xffffffffu, S0,   o);
        T0   += __shfl_down_sync(0xffffffffu, T0,   o);
        S1   += __shfl_down_sync(0xffffffffu, S1,   o);
        T1   += __shfl_down_sync(0xffffffffu, T1,   o);
    }
    if (lane == 0) {
        S[0*8 + wrp] = zacc;
        S[1*8 + wrp] = S0;
        S[2*8 + wrp] = T0 * 0.69314718056f;    // log2 -> ln
        S[3*8 + wrp] = S1;
        S[4*8 + wrp] = T1 * 0.69314718056f;
    }
    __syncthreads();
    if (tid < 5) {
        float a = 0.f;
        #pragma unroll
        for (int j = 0; j < 8; ++j) a += S[tid*8 + j];
        g_red[tid * NCHAN + ch] = a;
    }
    __threadfence();
    __syncthreads();
    if (tid == 0) s_last = (atomicAdd(&g_cnt, 1u) == (unsigned)(gridDim.x - 1));
    __syncthreads();
    if (!s_last) return;

    // ======================= HEAD (last block only) =======================
    __threadfence();

    for (int i = tid; i < 512; i += 256) ((float4*)(S+OFF_FC1W))[i] = ((const float4*)fc1_w)[i];
    for (int i = tid; i < 512; i += 256) ((float4*)(S+OFF_FC2W))[i] = ((const float4*)fc2_w)[i];
    for (int i = tid; i < 64;  i += 256) ((float4*)(S+OFF_C1W))[i]  = ((const float4*)cls1_w)[i];
    for (int i = tid; i < 160; i += 256) ((float4*)(S+OFF_C2W))[i]  = ((const float4*)cls2_w)[i];
    if (tid < 32)  S[OFF_F1B + tid] = fc1_b[tid];
    if (tid < 64)  S[OFF_F2B + tid] = fc2_b[tid];
    if (tid < 128) S[OFF_C1B + tid] = cls1_b[tid];
    if (tid < 5)   S[OFF_C2B + tid] = cls2_b[tid];
    for (int i = tid; i < NCHAN; i += 256) {       // z transposed z_T[c][b]
        int c = i >> 5, b = i & 31;
        S[OFF_Z + i] = __ldcg(&g_red[b * CH + c]) * (1.f / 65536.f);
    }
    __syncthreads();

    // h_T[j][b] = relu(z @ fc1_w^T + b)
    for (int i = tid; i < BATCH * 32; i += 256) {
        int j = i >> 5, b = i & 31;
        float acc = S[OFF_F1B + j];
        const float* wr = S + OFF_FC1W + j * CH;
        #pragma unroll
        for (int c = 0; c < CH; ++c) acc += S[OFF_Z + c*32 + b] * wr[c];
        S[OFF_H + j*32 + b] = fmaxf(acc, 0.f);
    }
    __syncthreads();

    // pre-softmax logits
    for (int i = tid; i < NCHAN; i += 256) {
        int c = i >> 5, b = i & 31;
        float acc = S[OFF_F2B + c];
        const float* wr = S + OFF_FC2W + c * 32;
        #pragma unroll
        for (int j = 0; j < 32; ++j) acc += S[OFF_H + j*32 + b] * wr[j];
        S[OFF_WSM + b*CH + c] = acc;
    }
    __syncthreads();

    // softmax per row
    for (int b = wrp; b < BATCH; b += 8) {
        float v0 = S[OFF_WSM + b*CH + lane];
        float v1 = S[OFF_WSM + b*CH + 32 + lane];
        float m = fmaxf(v0, v1);
        #pragma unroll
        for (int o = 16; o; o >>= 1) m = fmaxf(m, __shfl_xor_sync(0xffffffffu, m, o));
        float e0 = __expf(v0 - m), e1 = __expf(v1 - m);
        float s = e0 + e1;
        #pragma unroll
        for (int o = 16; o; o >>= 1) s += __shfl_xor_sync(0xffffffffu, s, o);
        float inv = 1.f / s;
        S[OFF_WSM + b*CH + lane]      = e0 * inv;
        S[OFF_WSM + b*CH + 32 + lane] = e1 * inv;
    }
    __syncthreads();

    // entropy closed form, write w
    for (int i = tid; i < NCHAN; i += 256) {
        float wv = S[OFF_WSM + i];
        out[BATCH*5 + i] = wv;
        float s0v = __ldcg(&g_red[1*NCHAN + i]);
        float t0v = __ldcg(&g_red[2*NCHAN + i]);
        float s1v = __ldcg(&g_red[3*NCHAN + i]);
        float t1v = __ldcg(&g_red[4*NCHAN + i]);
        float lw = __logf(wv);
        float a0 = wv * s0v, s0 = a0 + 1e-12f;
        float e0 = (a0 / s0) * (__logf(s0) - lw) - wv * t0v / s0;
        float a1 = wv * s1v, s1 = a1 + 1e-12f;
        float e1 = (a1 / s1) * (__logf(s1) - lw) - wv * t1v / s1;
        S[OFF_FC1W + i] = e0 * wv;
        S[OFF_FC2W + i] = e1 * wv;
    }
    __syncthreads();

    if (tid < BATCH * 2) {
        int b = tid >> 1, k = tid & 1;
        const float* cs = S + (k == 0 ? OFF_FC1W : OFF_FC2W) + b*CH;
        float acc = 0.f, ws = 0.f;
        #pragma unroll
        for (int c = 0; c < CH; ++c) { acc += cs[c]; ws += S[OFF_WSM + b*CH + c]; }
        float fv = acc / (ws + 1e-6f);
        S[OFF_FBUF + tid] = fv;
        out[BATCH*5 + NCHAN + tid] = fv;
    }
    __syncthreads();

    for (int i = tid; i < BATCH * 128; i += 256) {
        int b = i >> 7, j = i & 127;
        float mv = S[OFF_FBUF + 2*b] * S[OFF_C1W + 2*j]
                 + S[OFF_FBUF + 2*b + 1] * S[OFF_C1W + 2*j + 1]
                 + S[OFF_C1B + j];
        S[OFF_Z + i] = fmaxf(mv, 0.f);
    }
    __syncthreads();

    for (int i = tid; i < BATCH * 5; i += 256) {
        int b = i / 5, n = i - b * 5;
        float acc = S[OFF_C2B + n];
        const float* wr = S + OFF_C2W + n * 128;
        const float* mr = S + OFF_Z + b * 128;
        #pragma unroll
        for (int j = 0; j < 128; ++j) acc += mr[j] * wr[j];
        out[i] = acc;
    }
    if (tid == 0) g_cnt = 0;
}

extern "C" void kernel_launch(void* const* d_in, const int* in_sizes, int n_in,
                              void* d_out, int out_size) {
    const float* x      = (const float*)d_in[0];
    const float* fc1_w  = (const float*)d_in[1];
    const float* fc1_b  = (const float*)d_in[2];
    const float* fc2_w  = (const float*)d_in[3];
    const float* fc2_b  = (const float*)d_in[4];
    const float* cls1_w = (const float*)d_in[5];
    const float* cls1_b = (const float*)d_in[6];
    const float* cls2_w = (const float*)d_in[7];
    const float* cls2_b = (const float*)d_in[8];
    float* out = (float*)d_out;

    topo_fused_kernel<<<NCHAN, 256>>>(x, fc1_w, fc1_b, fc2_w, fc2_b,
                                      cls1_w, cls1_b, cls2_w, cls2_b, out);
}

// round 17
// speedup vs baseline: 1.0449x; 1.0189x over previous
#include <cuda_runtime.h>
#include <math.h>

#define BATCH 32
#define CH    64
#define HH    256
#define WW    256
#define NCHAN 2048

__device__ float g_red[5 * NCHAN];   // [0]=sum(x) [1]=S0 [2]=T0 [3]=S1 [4]=T1
__device__ unsigned int g_cnt = 0;

// ---- shared memory layout (floats) ----
#define OFF_FC1W 0
#define OFF_FC2W 2048
#define OFF_Z    4096
#define OFF_H    6144
#define OFF_WSM  7168
#define OFF_C1W  9216
#define OFF_C2W  9472
#define OFF_F1B  10112
#define OFF_F2B  10144
#define OFF_C1B  10208
#define OFF_C2B  10336
#define OFF_FBUF 10344
#define SMEM_FLOATS 10416

// packed f32x2 helpers (Blackwell FADD2/FFMA2 via PTX)
#define PACK2(d, lo, hi)  asm("mov.b64 %0, {%1, %2};" : "=l"(d) : "f"(lo), "f"(hi))
#define UNPK2(lo, hi, s)  asm("mov.b64 {%0, %1}, %2;" : "=f"(lo), "=f"(hi) : "l"(s))
#define ADDX2(d, a, b)    asm("add.rn.f32x2 %0, %1, %2;" : "=l"(d) : "l"(a), "l"(b))
#define FMAX2(d, a, b, c) asm("fma.rn.f32x2 %0, %1, %2, %3;" : "=l"(d) : "l"(a), "l"(b), "l"(c))

#define PF_L2(p) asm volatile("prefetch.global.L2 [%0];" :: "l"(p))

__device__ __forceinline__ void load8(const float* __restrict__ p, float* __restrict__ v) {
    float4 a = *(const float4*)p;
    float4 b = *(const float4*)(p + 4);
    v[0]=a.x; v[1]=a.y; v[2]=a.z; v[3]=a.w;
    v[4]=b.x; v[5]=b.y; v[6]=b.z; v[7]=b.w;
}

// Phase-P step: cur = v[P] (row r), next = v[(P+1)%3] (row r+1),
// prefetch row r+2 into v[(P+2)%3]; L2-prefetch row r+4 (distance-2, proven optimum).
template<int P>
__device__ __forceinline__ void topo_step(
    const float* __restrict__ pf, bool eL, bool eR,
    float (&v)[3][8], float (&prx)[8], float (&prn)[8],
    unsigned long long& Z01, unsigned long long& S01, unsigned long long& T01,
    unsigned long long eps2)
{
    constexpr int C = P;
    constexpr int N = (P + 1) % 3;
    constexpr int F = (P + 2) % 3;
    load8(pf, v[F]);
    PF_L2(pf + 2 * WW);

    const float* cur = v[C];
    const float* nx  = v[N];

    // vertical 3-row results for edge columns first (feed shuffles early)
    float vx7 = fmaxf(prx[7], nx[7]);
    float vn7 = fminf(prn[7], nx[7]);
    float vx0 = fmaxf(prx[0], nx[0]);
    float vn0 = fminf(prn[0], nx[0]);

    float Lxr = __shfl_up_sync(0xffffffffu, vx7, 1);
    float Lnr = __shfl_up_sync(0xffffffffu, vn7, 1);
    float Rxr = __shfl_down_sync(0xffffffffu, vx0, 1);
    float Rnr = __shfl_down_sync(0xffffffffu, vn0, 1);
    float ax = eL ? -INFINITY : Lxr;
    float an = eL ?  INFINITY : Lnr;
    float Rx = eR ? -INFINITY : Rxr;
    float Rn = eR ?  INFINITY : Rnr;

    float bx = vx0, bn = vn0;
    #pragma unroll
    for (int i = 0; i < 8; ++i) {
        float cx = (i < 7) ? fmaxf(prx[i+1], nx[i+1]) : Rx;
        float cn = (i < 7) ? fminf(prn[i+1], nx[i+1]) : Rn;
        float mx = fmaxf(ax, fmaxf(bx, cx));
        float mn = fminf(an, fminf(bn, cn));
        float y  = cur[i];
        float l0 = mx - y;
        float l1 = y - mn;
        unsigned long long l01, le01, lg01;
        PACK2(l01, l0, l1);
        ADDX2(le01, l01, eps2);            // (l0+eps, l1+eps)
        float le0, le1;
        UNPK2(le0, le1, le01);
        float lg0 = __log2f(le0);
        float lg1 = __log2f(le1);
        PACK2(lg01, lg0, lg1);
        ADDX2(S01, S01, l01);              // (S0,S1) += (l0,l1)
        FMAX2(T01, l01, lg01, T01);        // (T0,T1) += (l0,l1)*(lg0,lg1)
        ax = bx; bx = cx;
        an = bn; bn = cn;
    }
    // zacc over cur row: float4-aligned register pairs
    #pragma unroll
    for (int j = 0; j < 4; ++j) {
        unsigned long long y01;
        PACK2(y01, cur[2*j], cur[2*j+1]);
        ADDX2(Z01, Z01, y01);
    }
    #pragma unroll
    for (int i = 0; i < 8; ++i) {
        prx[i] = fmaxf(cur[i], nx[i]);
        prn[i] = fminf(cur[i], nx[i]);
    }
}

__global__ __launch_bounds__(256, 4)
void topo_fused_kernel(const float* __restrict__ x,
                       const float* __restrict__ fc1_w, const float* __restrict__ fc1_b,
                       const float* __restrict__ fc2_w, const float* __restrict__ fc2_b,
                       const float* __restrict__ cls1_w, const float* __restrict__ cls1_b,
                       const float* __restrict__ cls2_w, const float* __restrict__ cls2_b,
                       float* __restrict__ out)
{
    __shared__ __align__(16) float S[SMEM_FLOATS];
    __shared__ int s_last;

    const int ch   = blockIdx.x;
    const int tid  = threadIdx.x;
    const int wrp  = tid >> 5;
    const int lane = tid & 31;
    const bool eL = (lane == 0), eR = (lane == 31);
    const float* __restrict__ base = x + (size_t)ch * (HH * WW) + lane * 8;

    const int r0 = wrp * 32;                   // output rows r0 .. r0+31
    const int ra = (r0 == 0) ? 0 : (r0 - 1);

    float v[3][8], prx[8], prn[8];
    unsigned long long Z01 = 0, S01 = 0, T01 = 0, eps2;
    {
        float e = 1e-35f;
        PACK2(eps2, e, e);
    }

    {
        float vp[8];
        load8(base + ra * WW, vp);             // row r0-1 (clamped)
        load8(base + r0 * WW, v[0]);           // cur  = row r0
        load8(base + (r0 + 1) * WW, v[1]);     // next = row r0+1
        #pragma unroll
        for (int i = 0; i < 8; ++i) {
            prx[i] = fmaxf(vp[i], v[0][i]);
            prn[i] = fminf(vp[i], v[0][i]);
        }
    }

    // Main loop: 30 uniform steps (loads rows r0+2 .. r0+31, never OOB).
    const float* p = base + (r0 + 2) * WW;
    #pragma unroll 1
    for (int g = 0; g < 10; ++g) {
        topo_step<0>(p,        eL, eR, v, prx, prn, Z01, S01, T01, eps2);
        topo_step<1>(p + WW,   eL, eR, v, prx, prn, Z01, S01, T01, eps2);
        topo_step<2>(p + 2*WW, eL, eR, v, prx, prn, Z01, S01, T01, eps2);
        p += 3 * WW;
    }
    // Tail: out rows r0+30, r0+31; loads clamp to row 255 (warp 7 only).
    {
        const float* p30 = base + ((r0 + 32 > 255) ? 255 : (r0 + 32)) * WW;
        const float* p31 = base + ((r0 + 33 > 255) ? 255 : (r0 + 33)) * WW;
        topo_step<0>(p30, eL, eR, v, prx, prn, Z01, S01, T01, eps2);
        topo_step<1>(p31, eL, eR, v, prx, prn, Z01, S01, T01, eps2);
    }

    float za, zb, S0, S1, T0, T1;
    UNPK2(za, zb, Z01);
    UNPK2(S0, S1, S01);
    UNPK2(T0, T1, T01);
    float zacc = za + zb;

    // warp reduce 5 accumulators
    #pragma unroll
    for (int o = 16; o; o >>= 1) {
        zacc += __shfl_down_sync(0xffffffffu, zacc, o);
        S0   += __shfl_down_sync(0xffffffffu, S0,   o);
        T0   += __shfl_down_sync(0xffffffffu, T0,   o);
        S1   += __shfl_down_sync(0xffffffffu, S1,   o);
        T1   += __shfl_down_sync(0xffffffffu, T1,   o);
    }
    if (lane == 0) {
        S[0*8 + wrp] = zacc;
        S[1*8 + wrp] = S0;
        S[2*8 + wrp] = T0 * 0.69314718056f;    // log2 -> ln
        S[3*8 + wrp] = S1;
        S[4*8 + wrp] = T1 * 0.69314718056f;
    }
    __syncthreads();
    if (tid < 5) {
        float a = 0.f;
        #pragma unroll
        for (int j = 0; j < 8; ++j) a += S[tid*8 + j];
        g_red[tid * NCHAN + ch] = a;
    }
    __threadfence();
    __syncthreads();
    if (tid == 0) s_last = (atomicAdd(&g_cnt, 1u) == (unsigned)(gridDim.x - 1));
    __syncthreads();
    if (!s_last) return;

    // ======================= HEAD (last block only) =======================
    __threadfence();

    for (int i = tid; i < 512; i += 256) ((float4*)(S+OFF_FC1W))[i] = ((const float4*)fc1_w)[i];
    for (int i = tid; i < 512; i += 256) ((float4*)(S+OFF_FC2W))[i] = ((const float4*)fc2_w)[i];
    for (int i = tid; i < 64;  i += 256) ((float4*)(S+OFF_C1W))[i]  = ((const float4*)cls1_w)[i];
    for (int i = tid; i < 160; i += 256) ((float4*)(S+OFF_C2W))[i]  = ((const float4*)cls2_w)[i];
    if (tid < 32)  S[OFF_F1B + tid] = fc1_b[tid];
    if (tid < 64)  S[OFF_F2B + tid] = fc2_b[tid];
    if (tid < 128) S[OFF_C1B + tid] = cls1_b[tid];
    if (tid < 5)   S[OFF_C2B + tid] = cls2_b[tid];
    for (int i = tid; i < NCHAN; i += 256) {       // z transposed z_T[c][b]
        int c = i >> 5, b = i & 31;
        S[OFF_Z + i] = __ldcg(&g_red[b * CH + c]) * (1.f / 65536.f);
    }
    __syncthreads();

    // h_T[j][b] = relu(z @ fc1_w^T + b)
    for (int i = tid; i < BATCH * 32; i += 256) {
        int j = i >> 5, b = i & 31;
        float acc = S[OFF_F1B + j];
        const float* wr = S + OFF_FC1W + j * CH;
        #pragma unroll
        for (int c = 0; c < CH; ++c) acc += S[OFF_Z + c*32 + b] * wr[c];
        S[OFF_H + j*32 + b] = fmaxf(acc, 0.f);
    }
    __syncthreads();

    // pre-softmax logits
    for (int i = tid; i < NCHAN; i += 256) {
        int c = i >> 5, b = i & 31;
        float acc = S[OFF_F2B + c];
        const float* wr = S + OFF_FC2W + c * 32;
        #pragma unroll
        for (int j = 0; j < 32; ++j) acc += S[OFF_H + j*32 + b] * wr[j];
        S[OFF_WSM + b*CH + c] = acc;
    }
    __syncthreads();

    // softmax per row
    for (int b = wrp; b < BATCH; b += 8) {
        float v0 = S[OFF_WSM + b*CH + lane];
        float v1 = S[OFF_WSM + b*CH + 32 + lane];
        float m = fmaxf(v0, v1);
        #pragma unroll
        for (int o = 16; o; o >>= 1) m = fmaxf(m, __shfl_xor_sync(0xffffffffu, m, o));
        float e0 = __expf(v0 - m), e1 = __expf(v1 - m);
        float s = e0 + e1;
        #pragma unroll
        for (int o = 16; o; o >>= 1) s += __shfl_xor_sync(0xffffffffu, s, o);
        float inv = 1.f / s;
        S[OFF_WSM + b*CH + lane]      = e0 * inv;
        S[OFF_WSM + b*CH + 32 + lane] = e1 * inv;
    }
    __syncthreads();

    // entropy closed form, write w
    for (int i = tid; i < NCHAN; i += 256) {
        float wv = S[OFF_WSM + i];
        out[BATCH*5 + i] = wv;
        float s0v = __ldcg(&g_red[1*NCHAN + i]);
        float t0v = __ldcg(&g_red[2*NCHAN + i]);
        float s1v = __ldcg(&g_red[3*NCHAN + i]);
        float t1v = __ldcg(&g_red[4*NCHAN + i]);
        float lw = __logf(wv);
        float a0 = wv * s0v, s0 = a0 + 1e-12f;
        float e0 = (a0 / s0) * (__logf(s0) - lw) - wv * t0v / s0;
        float a1 = wv * s1v, s1 = a1 + 1e-12f;
        float e1 = (a1 / s1) * (__logf(s1) - lw) - wv * t1v / s1;
        S[OFF_FC1W + i] = e0 * wv;
        S[OFF_FC2W + i] = e1 * wv;
    }
    __syncthreads();

    if (tid < BATCH * 2) {
        int b = tid >> 1, k = tid & 1;
        const float* cs = S + (k == 0 ? OFF_FC1W : OFF_FC2W) + b*CH;
        float acc = 0.f, ws = 0.f;
        #pragma unroll
        for (int c = 0; c < CH; ++c) { acc += cs[c]; ws += S[OFF_WSM + b*CH + c]; }
        float fv = acc / (ws + 1e-6f);
        S[OFF_FBUF + tid] = fv;
        out[BATCH*5 + NCHAN + tid] = fv;
    }
    __syncthreads();

    for (int i = tid; i < BATCH * 128; i += 256) {
        int b = i >> 7, j = i & 127;
        float mv = S[OFF_FBUF + 2*b] * S[OFF_C1W + 2*j]
                 + S[OFF_FBUF + 2*b + 1] * S[OFF_C1W + 2*j + 1]
                 + S[OFF_C1B + j];
        S[OFF_Z + i] = fmaxf(mv, 0.f);
    }
    __syncthreads();

    for (int i = tid; i < BATCH * 5; i += 256) {
        int b = i / 5, n = i - b * 5;
        float acc = S[OFF_C2B + n];
        const float* wr = S + OFF_C2W + n * 128;
        const float* mr = S + OFF_Z + b * 128;
        #pragma unroll
        for (int j = 0; j < 128; ++j) acc += mr[j] * wr[j];
        out[i] = acc;
    }
    if (tid == 0) g_cnt = 0;
}

extern "C" void kernel_launch(void* const* d_in, const int* in_sizes, int n_in,
                              void* d_out, int out_size) {
    const float* x      = (const float*)d_in[0];
    const float* fc1_w  = (const float*)d_in[1];
    const float* fc1_b  = (const float*)d_in[2];
    const float* fc2_w  = (const float*)d_in[3];
    const float* fc2_b  = (const float*)d_in[4];
    const float* cls1_w = (const float*)d_in[5];
    const float* cls1_b = (const float*)d_in[6];
    const float* cls2_w = (const float*)d_in[7];
    const float* cls2_b = (const float*)d_in[8];
    float* out = (float*)d_out;

    topo_fused_kernel<<<NCHAN, 256>>>(x, fc1_w, fc1_b, fc2_w, fc2_b,
                                      cls1_w, cls1_b, cls2_w, cls2_b, out);
}